// round 6
// baseline (speedup 1.0000x reference)
#include <cuda_runtime.h>

#define THREADS 256
#define NQ 12
#define DIM 4096

using u64 = unsigned long long;

// ---- packed f32x2 helpers ----
__device__ __forceinline__ u64 pk2(float lo, float hi) {
    u64 r; asm("mov.b64 %0,{%1,%2};" : "=l"(r) : "f"(lo), "f"(hi)); return r;
}
__device__ __forceinline__ void upk2(u64 v, float& lo, float& hi) {
    asm("mov.b64 {%0,%1},%2;" : "=f"(lo), "=f"(hi) : "l"(v));
}
__device__ __forceinline__ u64 fma2(u64 a, u64 b, u64 c) {
    u64 d; asm("fma.rn.f32x2 %0,%1,%2,%3;" : "=l"(d) : "l"(a), "l"(b), "l"(c)); return d;
}
__device__ __forceinline__ u64 mul2(u64 a, u64 b) {
    u64 d; asm("mul.rn.f32x2 %0,%1,%2;" : "=l"(d) : "l"(a), "l"(b)); return d;
}

// XOR swizzle on float2-indexed shared state (conflict-free for all patterns)
__device__ __forceinline__ int swz(int i) { return i ^ ((i >> 4) & 15); }

// Ring-CNOT permutation: new_state[i] = old_state[perm_fwd(i)]
__device__ __forceinline__ int perm_fwd(int i) {
#pragma unroll
    for (int j = 11; j >= 0; j--) {
        int cb = 11 - j;
        int tb = (j == 11) ? 11 : (10 - j);
        i ^= ((i >> cb) & 1) << tb;
    }
    return i;
}
__device__ __forceinline__ int perm_inv(int i) {
#pragma unroll
    for (int j = 0; j < 12; j++) {
        int cb = 11 - j;
        int tb = (j == 11) ? 11 : (10 - j);
        i ^= ((i >> cb) & 1) << tb;
    }
    return i;
}

__global__ void __launch_bounds__(THREADS, 4) qsim_kernel(
    const float* __restrict__ x, const float* __restrict__ w,
    float* __restrict__ out)
{
    __shared__ float2 st[DIM];          // 32 KB state, swizzled
    __shared__ float gc[48], gs[48];    // cos/sin (0-11 = merged encode+layer0)
    __shared__ float gt[48];            // tan(theta/2) (slots 12-47 consumed)
    __shared__ float sLA[16], sLB[16], sLC[16];  // product-state magnitude LUTs
    __shared__ float red[NQ];
    __shared__ float sS2;               // (prod of c over gates 12..47)^2

    const int b = blockIdx.x;
    const int t = threadIdx.x;
    const int pt = perm_fwd(t);         // cached; used by 3 perm-folded passes

    // Angles. Slots 0-11: theta = x_q + w_{0,q} (RX fusion). 12-47: w rows 1-3.
    if (t < 48) {
        float th = w[t];
        if (t < NQ) th += x[b * NQ + t];
        float ss, cc;
        sincosf(0.5f * th, &ss, &cc);
        gc[t] = cc; gs[t] = ss;
        gt[t] = ss / cc;
    }
    if (t < NQ) red[t] = 0.0f;
    __syncthreads();

    // Product-state magnitude LUTs over the three 4-bit nibbles (exact c,s).
    if (t < 48) {
        int grp = t >> 4;
        int h = t & 15;
        int qbase = grp * 4;
        float p = 1.0f;
#pragma unroll
        for (int q = 0; q < 4; q++)
            p *= ((h >> (3 - q)) & 1) ? gs[qbase + q] : gc[qbase + q];
        (grp == 0 ? sLA : grp == 1 ? sLB : sLC)[h] = p;
    }
    if (t == 0) {
        float S = 1.0f;
#pragma unroll
        for (int g = 12; g < 48; g++) S *= gc[g];
        sS2 = S * S;
    }

    u64 X[8], Y[8];  // SoA packed state: pack k holds amps l=2k, 2k+1

    auto lidx = [&](int shift, int l) -> int {
        if (shift == 8) return (l << 8) | t;
        if (shift == 4) return ((t >> 4) << 8) | (l << 4) | (t & 15);
        return (t << 4) | l;
    };

    // pack-bit gate (l-mask 1) in tangent form on a freshly loaded pair, pack.
    auto gate_pack = [&](float2 a0, float2 a1, float t1, int k) {
        float nx0 = fmaf( t1, a1.y, a0.x);
        float ny0 = fmaf(-t1, a1.x, a0.y);
        float nx1 = fmaf( t1, a0.y, a1.x);
        float ny1 = fmaf(-t1, a0.x, a1.y);
        X[k] = pk2(nx0, nx1);
        Y[k] = pk2(ny0, ny1);
    };

    // Packed tangent-form RX on pack-space bit pm: 4 wide FMAs per pair.
    auto rxp = [&](int g, int pm) {
        float tg = gt[g];
        u64 t2 = pk2(tg, tg), m2 = pk2(-tg, -tg);
#pragma unroll
        for (int k = 0; k < 8; k++) {
            if (!(k & pm)) {
                int k1 = k | pm;
                u64 X0 = X[k], Y0 = Y[k], X1 = X[k1], Y1 = Y[k1];
                X[k]  = fma2(t2, Y1, X0);
                Y[k]  = fma2(m2, X1, Y0);
                X[k1] = fma2(t2, Y0, X1);
                Y[k1] = fma2(m2, X0, Y1);
            }
        }
    };
    auto packed3 = [&](int g) { rxp(g, 4); rxp(g + 1, 2); rxp(g + 2, 1); };

    auto load_pass = [&](int g, int shift) {
        float t1 = gt[g + 3];
#pragma unroll
        for (int k = 0; k < 8; k++)
            gate_pack(st[swz(lidx(shift, 2 * k))], st[swz(lidx(shift, 2 * k + 1))],
                      t1, k);
    };
    auto load_pass_perm = [&](int g) {
        float t1 = gt[g + 3];
#pragma unroll
        for (int k = 0; k < 8; k++)
            gate_pack(st[swz(perm_fwd((2 * k) << 8) ^ pt)],
                      st[swz(perm_fwd((2 * k + 1) << 8) ^ pt)], t1, k);
    };
    auto store_pass = [&](int shift) {
#pragma unroll
        for (int k = 0; k < 8; k++) {
            float x0, x1, y0, y1;
            upk2(X[k], x0, x1);
            upk2(Y[k], y0, y1);
            st[swz(lidx(shift, 2 * k))]     = make_float2(x0, y0);
            st[swz(lidx(shift, 2 * k + 1))] = make_float2(x1, y1);
        }
    };

    // Analytic product-state amplitude: amp = mag(pi) * (-i)^popc(pi)
    auto prod_amp = [&](int pi) -> float2 {
        float mag = sLA[pi >> 8] * sLB[(pi >> 4) & 15] * sLC[pi & 15];
        int kc = __popc(pi) & 3;
        float sm = __int_as_float(__float_as_int(mag) ^ (((kc + 1) & 2) << 30));
        return (kc & 1) ? make_float2(0.0f, sm) : make_float2(sm, 0.0f);
    };

    __syncthreads();  // LUTs + sS2 ready

    // ---- Layer 1 (gates 12-23): group A analytic at perm-permuted indices ----
    {
        float t1 = gt[15];
#pragma unroll
        for (int k = 0; k < 8; k++)
            gate_pack(prod_amp(perm_fwd((2 * k) << 8) ^ pt),
                      prod_amp(perm_fwd((2 * k + 1) << 8) ^ pt), t1, k);
        packed3(12);
        store_pass(8); __syncthreads();

        load_pass(16, 4); packed3(16); store_pass(4); __syncthreads();
        load_pass(20, 0); packed3(20); store_pass(0); __syncthreads();
    }

    // ---- Layers 2,3 (gates 24-35, 36-47) ----
#pragma unroll 1
    for (int layer = 2; layer <= 3; layer++) {
        int g = layer * 12;
        load_pass_perm(g);
        packed3(g);
        __syncthreads();     // scattered reads done before overwrite
        store_pass(8); __syncthreads();

        load_pass(g + 4, 4); packed3(g + 4); store_pass(4); __syncthreads();

        load_pass(g + 8, 0); packed3(g + 8);
        if (layer < 3) { store_pass(0); __syncthreads(); }
        // layer 3: stays in registers; final perm folded into readout
    }

    // ---- Readout: <Z_q> = S^2 * sum_i p_i * (1-2*bit_{11-q}(perm(i))) ----
    // Packed accumulation: acc2[q] += sign2(k,q) * P_k with sign2 one of 4
    // preloaded packed +/-1 constants (compile-time selected per (k,q)).
    u64 acc2[NQ];
    const u64 spp = pk2( 1.0f,  1.0f), spm = pk2( 1.0f, -1.0f);
    const u64 smp = pk2(-1.0f,  1.0f), smm = pk2(-1.0f, -1.0f);
#pragma unroll
    for (int q = 0; q < NQ; q++) acc2[q] = 0ull;
#pragma unroll
    for (int k = 0; k < 8; k++) {
        u64 P = fma2(X[k], X[k], mul2(Y[k], Y[k]));
        const int pil0 = perm_inv(2 * k);      // compile-time constants
        const int pil1 = perm_inv(2 * k + 1);
#pragma unroll
        for (int q = 0; q < NQ; q++) {
            bool n0 = (pil0 >> (11 - q)) & 1;
            bool n1 = (pil1 >> (11 - q)) & 1;
            u64 sgn = n0 ? (n1 ? smm : smp) : (n1 ? spm : spp);
            acc2[q] = fma2(sgn, P, acc2[q]);
        }
    }
    float acc[NQ];
    {
        int pit = perm_inv(t << 4);  // runtime per-thread sign factor
#pragma unroll
        for (int q = 0; q < NQ; q++) {
            float a0, a1;
            upk2(acc2[q], a0, a1);
            float s = a0 + a1;
            acc[q] = __int_as_float(__float_as_int(s) ^
                                    (((pit >> (11 - q)) & 1) << 31));
        }
    }
#pragma unroll
    for (int off = 16; off > 0; off >>= 1) {
#pragma unroll
        for (int q = 0; q < NQ; q++)
            acc[q] += __shfl_xor_sync(0xffffffffu, acc[q], off);
    }
    if ((t & 31) == 0) {
#pragma unroll
        for (int q = 0; q < NQ; q++) atomicAdd(&red[q], acc[q]);
    }
    __syncthreads();
    if (t < NQ) out[b * NQ + t] = red[t] * sS2;  // apply deferred scale once

}

extern "C" void kernel_launch(void* const* d_in, const int* in_sizes, int n_in,
                              void* d_out, int out_size) {
    const float* x = (const float*)d_in[0];   // (64,128,12) float32
    const float* w = (const float*)d_in[1];   // (4,12) float32
    float* out = (float*)d_out;               // (64,128,12) float32
    int B = in_sizes[0] / NQ;                 // 8192
    qsim_kernel<<<B, THREADS>>>(x, w, out);
}

// round 7
// speedup vs baseline: 1.0576x; 1.0576x over previous
#include <cuda_runtime.h>

#define THREADS 256
#define NQ 12
#define DIM 4096

// XOR swizzle on float2-indexed shared state (conflict-free for all patterns)
__device__ __forceinline__ int swz(int i) { return i ^ ((i >> 4) & 15); }

// Ring-CNOT permutation: new_state[i] = old_state[perm_fwd(i)]
__device__ __forceinline__ int perm_fwd(int i) {
#pragma unroll
    for (int j = 11; j >= 0; j--) {
        int cb = 11 - j;
        int tb = (j == 11) ? 11 : (10 - j);
        i ^= ((i >> cb) & 1) << tb;
    }
    return i;
}
__device__ __forceinline__ int perm_inv(int i) {
#pragma unroll
    for (int j = 0; j < 12; j++) {
        int cb = 11 - j;
        int tb = (j == 11) ? 11 : (10 - j);
        i ^= ((i >> cb) & 1) << tb;
    }
    return i;
}

__global__ void __launch_bounds__(THREADS, 3) qsim_kernel(
    const float* __restrict__ x, const float* __restrict__ w,
    float* __restrict__ out)
{
    __shared__ float2 st[DIM];          // 32 KB state, swizzled
    __shared__ float gc[48], gs[48];    // cos/sin (0-11 = merged encode+layer0)
    __shared__ float gt[48];            // tan(theta/2) (slots 12-47 consumed)
    __shared__ float sLA[16], sLB[16], sLC[16];  // product-state magnitude LUTs
    __shared__ float red[NQ];
    __shared__ float sS2;               // (prod of c over gates 12..47)^2

    const int b = blockIdx.x;
    const int t = threadIdx.x;
    const int pt = perm_fwd(t);         // used by the 3 perm-folded passes

    // Angles. Slots 0-11: theta = x_q + w_{0,q} (RX fusion). 12-47: w rows 1-3.
    if (t < 48) {
        float th = w[t];
        if (t < NQ) th += x[b * NQ + t];
        float ss, cc;
        sincosf(0.5f * th, &ss, &cc);
        gc[t] = cc; gs[t] = ss;
        gt[t] = ss / cc;
    }
    if (t < NQ) red[t] = 0.0f;
    __syncthreads();

    // Product-state magnitude LUTs over the three 4-bit nibbles (exact c,s).
    if (t < 48) {
        int grp = t >> 4;
        int h = t & 15;
        int qbase = grp * 4;
        float p = 1.0f;
#pragma unroll
        for (int q = 0; q < 4; q++)
            p *= ((h >> (3 - q)) & 1) ? gs[qbase + q] : gc[qbase + q];
        (grp == 0 ? sLA : grp == 1 ? sLB : sLC)[h] = p;
    }
    if (t == 0) {
        float S = 1.0f;
#pragma unroll
        for (int g = 12; g < 48; g++) S *= gc[g];
        sS2 = S * S;
    }

    float2 a[16];  // 16 amplitudes spanning the group's 4 index bits

    auto lidx = [&](int shift, int l) -> int {
        if (shift == 8) return (l << 8) | t;
        if (shift == 4) return ((t >> 4) << 8) | (l << 4) | (t & 15);
        return (t << 4) | l;
    };

    // Tangent-form RX on in-register bit mask m: 1 FMA per output value.
    auto rx = [&](int g, int m) {
        float tg = gt[g];
#pragma unroll
        for (int l = 0; l < 16; l++) {
            if (!(l & m)) {
                int l1 = l | m;
                float2 a0 = a[l], a1 = a[l1];
                a[l].x  = fmaf( tg, a1.y, a0.x);
                a[l].y  = fmaf(-tg, a1.x, a0.y);
                a[l1].x = fmaf( tg, a0.y, a1.x);
                a[l1].y = fmaf(-tg, a0.x, a1.y);
            }
        }
    };
    auto rx4 = [&](int g) { rx(g, 8); rx(g + 1, 4); rx(g + 2, 2); rx(g + 3, 1); };

    auto load = [&](int shift) {
#pragma unroll
        for (int l = 0; l < 16; l++) a[l] = st[swz(lidx(shift, l))];
    };
    auto load_perm = [&]() {
#pragma unroll
        for (int l = 0; l < 16; l++) a[l] = st[swz(perm_fwd(l << 8) ^ pt)];
    };
    auto store = [&](int shift) {
#pragma unroll
        for (int l = 0; l < 16; l++) st[swz(lidx(shift, l))] = a[l];
    };

    // Analytic product-state amplitude: amp = mag(pi) * (-i)^popc(pi)
    auto prod_amp = [&](int pi) -> float2 {
        float mag = sLA[pi >> 8] * sLB[(pi >> 4) & 15] * sLC[pi & 15];
        int kc = __popc(pi) & 3;
        float sm = __int_as_float(__float_as_int(mag) ^ (((kc + 1) & 2) << 30));
        return (kc & 1) ? make_float2(0.0f, sm) : make_float2(sm, 0.0f);
    };

    __syncthreads();  // LUTs + sS2 ready

    // ---- Layer 1 (gates 12-23): group A analytic at perm-permuted indices ----
    {
#pragma unroll
        for (int l = 0; l < 16; l++)
            a[l] = prod_amp(perm_fwd(l << 8) ^ pt);
        rx4(12);
        store(8); __syncthreads();

        load(4); rx4(16); store(4); __syncthreads();
        load(0); rx4(20); store(0); __syncthreads();
    }

    // ---- Layers 2,3 (gates 24-35, 36-47) ----
#pragma unroll 1
    for (int layer = 2; layer <= 3; layer++) {
        int g = layer * 12;
        load_perm();         // scattered reads fold in the previous perm
        rx4(g);
        __syncthreads();     // reads complete before overwrite
        store(8); __syncthreads();

        load(4); rx4(g + 4); store(4); __syncthreads();

        load(0); rx4(g + 8);
        if (layer < 3) { store(0); __syncthreads(); }
        // layer 3: stays in registers; final perm folded into readout
    }

    // ---- Readout: <Z_q> = S^2 * sum_i p_i * (1-2*bit_{11-q}(perm(i))) ----
    // sign(l,q) compile-time (FADD neg modifier); sign_t(q) via 1 XOR at end.
    float acc[NQ];
#pragma unroll
    for (int q = 0; q < NQ; q++) acc[q] = 0.0f;
#pragma unroll
    for (int l = 0; l < 16; l++) {
        float p = fmaf(a[l].x, a[l].x, a[l].y * a[l].y);
        const int pil = perm_inv(l);   // compile-time constant
#pragma unroll
        for (int q = 0; q < NQ; q++)
            acc[q] += ((pil >> (11 - q)) & 1) ? -p : p;
    }
    {
        int pit = perm_inv(t << 4);    // runtime per-thread sign factor
#pragma unroll
        for (int q = 0; q < NQ; q++)
            acc[q] = __int_as_float(__float_as_int(acc[q]) ^
                                    (((pit >> (11 - q)) & 1) << 31));
    }
#pragma unroll
    for (int off = 16; off > 0; off >>= 1) {
#pragma unroll
        for (int q = 0; q < NQ; q++)
            acc[q] += __shfl_xor_sync(0xffffffffu, acc[q], off);
    }
    if ((t & 31) == 0) {
#pragma unroll
        for (int q = 0; q < NQ; q++) atomicAdd(&red[q], acc[q]);
    }
    __syncthreads();
    if (t < NQ) out[b * NQ + t] = red[t] * sS2;  // apply deferred scale once
}

extern "C" void kernel_launch(void* const* d_in, const int* in_sizes, int n_in,
                              void* d_out, int out_size) {
    const float* x = (const float*)d_in[0];   // (64,128,12) float32
    const float* w = (const float*)d_in[1];   // (4,12) float32
    float* out = (float*)d_out;               // (64,128,12) float32
    int B = in_sizes[0] / NQ;                 // 8192
    qsim_kernel<<<B, THREADS>>>(x, w, out);
}

// round 9
// speedup vs baseline: 1.1774x; 1.1133x over previous
#include <cuda_runtime.h>

#define THREADS 256
#define NQ 12
#define DIM 4096

using u64 = unsigned long long;

// ---- packed f32x2 helpers ----
__device__ __forceinline__ u64 pk2(float lo, float hi) {
    u64 r; asm("mov.b64 %0,{%1,%2};" : "=l"(r) : "f"(lo), "f"(hi)); return r;
}
__device__ __forceinline__ void upk2(u64 v, float& lo, float& hi) {
    asm("mov.b64 {%0,%1},%2;" : "=f"(lo), "=f"(hi) : "l"(v));
}
__device__ __forceinline__ u64 fma2(u64 a, u64 b, u64 c) {
    u64 d; asm("fma.rn.f32x2 %0,%1,%2,%3;" : "=l"(d) : "l"(a), "l"(b), "l"(c)); return d;
}
__device__ __forceinline__ u64 mul2(u64 a, u64 b) {
    u64 d; asm("mul.rn.f32x2 %0,%1,%2;" : "=l"(d) : "l"(a), "l"(b)); return d;
}

// Bit0-preserving XOR swizzle (bits 3..1 ^= bits 6..4): keeps logical pairs
// (2k,2k+1) physically adjacent for float4 group-C passes while staying
// conflict-free for group A/B float2 patterns.
__device__ __forceinline__ int swz(int i) { return i ^ (((i >> 4) & 7) << 1); }

// Ring-CNOT permutation: new_state[i] = old_state[perm_fwd(i)]
__device__ __forceinline__ int perm_fwd(int i) {
#pragma unroll
    for (int j = 11; j >= 0; j--) {
        int cb = 11 - j;
        int tb = (j == 11) ? 11 : (10 - j);
        i ^= ((i >> cb) & 1) << tb;
    }
    return i;
}
__device__ __forceinline__ int perm_inv(int i) {
#pragma unroll
    for (int j = 0; j < 12; j++) {
        int cb = 11 - j;
        int tb = (j == 11) ? 11 : (10 - j);
        i ^= ((i >> cb) & 1) << tb;
    }
    return i;
}

__global__ void __launch_bounds__(THREADS, 3) qsim_kernel(
    const float* __restrict__ x, const float* __restrict__ w,
    float* __restrict__ out)
{
    __shared__ float2 st[DIM];          // 32 KB state, swizzled
    __shared__ float gc[48], gs[48];    // cos/sin (0-11 = merged encode+layer0)
    __shared__ float gt[48];            // tan(theta/2) (slots 12-47 consumed)
    __shared__ float sLA[16], sLB[16], sLC[16];  // product-state magnitude LUTs
    __shared__ float red[NQ];
    __shared__ float sS2;               // (prod of c over gates 12..47)^2

    const int b = blockIdx.x;
    const int t = threadIdx.x;
    const int pt = perm_fwd(t);         // used by the 3 perm-folded passes

    // Angles. Slots 0-11: theta = x_q + w_{0,q} (RX fusion). 12-47: w rows 1-3.
    if (t < 48) {
        float th = w[t];
        if (t < NQ) th += x[b * NQ + t];
        float ss, cc;
        sincosf(0.5f * th, &ss, &cc);
        gc[t] = cc; gs[t] = ss;
        gt[t] = ss / cc;
    }
    if (t < NQ) red[t] = 0.0f;
    __syncthreads();

    // Product-state magnitude LUTs over the three 4-bit nibbles (exact c,s).
    if (t < 48) {
        int grp = t >> 4;
        int h = t & 15;
        int qbase = grp * 4;
        float p = 1.0f;
#pragma unroll
        for (int q = 0; q < 4; q++)
            p *= ((h >> (3 - q)) & 1) ? gs[qbase + q] : gc[qbase + q];
        (grp == 0 ? sLA : grp == 1 ? sLB : sLC)[h] = p;
    }
    if (t == 0) {
        float S = 1.0f;
#pragma unroll
        for (int g = 12; g < 48; g++) S *= gc[g];
        sS2 = S * S;
    }

    u64 X[8], Y[8];  // SoA packed state: slot k holds LOGICAL amps l=2k, 2k+1

    auto lidx = [&](int shift, int l) -> int {
        if (shift == 8) return (l << 8) | t;
        return ((t >> 4) << 8) | (l << 4) | (t & 15);  // shift == 4
    };

    // pack-bit gate (l-mask 1) in tangent form on a freshly loaded pair, pack.
    auto gate_pack = [&](float2 a0, float2 a1, float t1, int k) {
        float nx0 = fmaf( t1, a1.y, a0.x);
        float ny0 = fmaf(-t1, a1.x, a0.y);
        float nx1 = fmaf( t1, a0.y, a1.x);
        float ny1 = fmaf(-t1, a0.x, a1.y);
        X[k] = pk2(nx0, nx1);
        Y[k] = pk2(ny0, ny1);
    };

    // Packed tangent-form RX on pack-space bit pm: 4 wide FMAs per pair.
    auto rxp = [&](int g, int pm) {
        float tg = gt[g];
        u64 t2 = pk2(tg, tg), m2 = pk2(-tg, -tg);
#pragma unroll
        for (int k = 0; k < 8; k++) {
            if (!(k & pm)) {
                int k1 = k | pm;
                u64 X0 = X[k], Y0 = Y[k], X1 = X[k1], Y1 = Y[k1];
                X[k]  = fma2(t2, Y1, X0);
                Y[k]  = fma2(m2, X1, Y0);
                X[k1] = fma2(t2, Y0, X1);
                Y[k1] = fma2(m2, X0, Y1);
            }
        }
    };
    auto packed3 = [&](int g) { rxp(g, 4); rxp(g + 1, 2); rxp(g + 2, 1); };

    auto load_pass = [&](int g, int shift) {
        float t1 = gt[g + 3];
#pragma unroll
        for (int k = 0; k < 8; k++)
            gate_pack(st[swz(lidx(shift, 2 * k))], st[swz(lidx(shift, 2 * k + 1))],
                      t1, k);
    };
    auto load_pass_perm = [&](int g) {
        float t1 = gt[g + 3];
#pragma unroll
        for (int k = 0; k < 8; k++)
            gate_pack(st[swz(perm_fwd((2 * k) << 8) ^ pt)],
                      st[swz(perm_fwd((2 * k + 1) << 8) ^ pt)], t1, k);
    };
    auto store_pass = [&](int shift) {
#pragma unroll
        for (int k = 0; k < 8; k++) {
            float x0, x1, y0, y1;
            upk2(X[k], x0, x1);
            upk2(Y[k], y0, y1);
            st[swz(lidx(shift, 2 * k))]     = make_float2(x0, y0);
            st[swz(lidx(shift, 2 * k + 1))] = make_float2(x1, y1);
        }
    };

    // Group C (bits 3..0) via float4. The float4 at physical index
    // (t<<3)|m holds LOGICAL pair m^e3 (swizzle XORs bits 3..1 by e3).
    // Loading address (t<<3)|(k^e3) therefore yields logical pair k -> slot k
    // (labels preserved), and addr4 mod 8 = k^(t&7) is distinct across 8
    // consecutive lanes -> conflict-free.
    const int e3 = t & 7;
    auto load_passC = [&](int g) {
        float t1 = gt[g + 3];
        const float4* st4 = reinterpret_cast<const float4*>(st);
#pragma unroll
        for (int k = 0; k < 8; k++) {
            float4 v = st4[(t << 3) | (k ^ e3)];
            gate_pack(make_float2(v.x, v.y), make_float2(v.z, v.w), t1, k);
        }
    };
    auto store_passC = [&]() {
        float4* st4 = reinterpret_cast<float4*>(st);
#pragma unroll
        for (int k = 0; k < 8; k++) {
            float x0, x1, y0, y1;
            upk2(X[k], x0, x1);
            upk2(Y[k], y0, y1);
            st4[(t << 3) | (k ^ e3)] = make_float4(x0, y0, x1, y1);
        }
    };

    // Analytic product-state amplitude: amp = mag(pi) * (-i)^popc(pi)
    auto prod_amp = [&](int pi) -> float2 {
        float mag = sLA[pi >> 8] * sLB[(pi >> 4) & 15] * sLC[pi & 15];
        int kc = __popc(pi) & 3;
        float sm = __int_as_float(__float_as_int(mag) ^ (((kc + 1) & 2) << 30));
        return (kc & 1) ? make_float2(0.0f, sm) : make_float2(sm, 0.0f);
    };

    __syncthreads();  // LUTs + sS2 ready

    // ---- Layer 1 (gates 12-23): group A analytic at perm-permuted indices ----
    {
        float t1 = gt[15];
#pragma unroll
        for (int k = 0; k < 8; k++)
            gate_pack(prod_amp(perm_fwd((2 * k) << 8) ^ pt),
                      prod_amp(perm_fwd((2 * k + 1) << 8) ^ pt), t1, k);
        packed3(12);
        store_pass(8); __syncthreads();

        load_pass(16, 4); packed3(16); store_pass(4);
        __syncwarp();                        // B->C exchange is intra-16-group
        load_passC(20); packed3(20); store_passC(); __syncthreads();
    }

    // ---- Layers 2,3 (gates 24-35, 36-47) ----
#pragma unroll 1
    for (int layer = 2; layer <= 3; layer++) {
        int g = layer * 12;
        load_pass_perm(g);
        packed3(g);
        __syncthreads();     // scattered reads complete before overwrite
        store_pass(8); __syncthreads();

        load_pass(g + 4, 4); packed3(g + 4); store_pass(4);
        __syncwarp();                        // B->C intra-warp

        load_passC(g + 8); packed3(g + 8);
        if (layer < 3) { store_passC(); __syncthreads(); }
        // layer 3: stays in registers (slot k = logical pair k);
        // final perm folded into readout
    }

    // ---- Readout: <Z_q> = S^2 * sum_i p_i * (1-2*bit_{11-q}(perm(i))) ----
    u64 acc2[NQ];
    const u64 spp = pk2( 1.0f,  1.0f), spm = pk2( 1.0f, -1.0f);
    const u64 smp = pk2(-1.0f,  1.0f), smm = pk2(-1.0f, -1.0f);
#pragma unroll
    for (int q = 0; q < NQ; q++) acc2[q] = 0ull;
#pragma unroll
    for (int k = 0; k < 8; k++) {
        u64 P = fma2(X[k], X[k], mul2(Y[k], Y[k]));
        const int pil0 = perm_inv(2 * k);      // compile-time constants
        const int pil1 = perm_inv(2 * k + 1);
#pragma unroll
        for (int q = 0; q < NQ; q++) {
            bool n0 = (pil0 >> (11 - q)) & 1;
            bool n1 = (pil1 >> (11 - q)) & 1;
            u64 sgn = n0 ? (n1 ? smm : smp) : (n1 ? spm : spp);
            acc2[q] = fma2(sgn, P, acc2[q]);
        }
    }
    float acc[NQ];
    {
        int pit = perm_inv(t << 4);  // runtime per-thread sign factor
#pragma unroll
        for (int q = 0; q < NQ; q++) {
            float a0, a1;
            upk2(acc2[q], a0, a1);
            float s = a0 + a1;
            acc[q] = __int_as_float(__float_as_int(s) ^
                                    (((pit >> (11 - q)) & 1) << 31));
        }
    }
#pragma unroll
    for (int off = 16; off > 0; off >>= 1) {
#pragma unroll
        for (int q = 0; q < NQ; q++)
            acc[q] += __shfl_xor_sync(0xffffffffu, acc[q], off);
    }
    if ((t & 31) == 0) {
#pragma unroll
        for (int q = 0; q < NQ; q++) atomicAdd(&red[q], acc[q]);
    }
    __syncthreads();
    if (t < NQ) out[b * NQ + t] = red[t] * sS2;  // apply deferred scale once
}

extern "C" void kernel_launch(void* const* d_in, const int* in_sizes, int n_in,
                              void* d_out, int out_size) {
    const float* x = (const float*)d_in[0];   // (64,128,12) float32
    const float* w = (const float*)d_in[1];   // (4,12) float32
    float* out = (float*)d_out;               // (64,128,12) float32
    int B = in_sizes[0] / NQ;                 // 8192
    qsim_kernel<<<B, THREADS>>>(x, w, out);
}

// round 12
// speedup vs baseline: 1.4086x; 1.1963x over previous
#include <cuda_runtime.h>

#define THREADS 64
#define NQ 12
#define DIM 4096

using u64 = unsigned long long;

// ---- packed f32x2 helpers ----
__device__ __forceinline__ u64 pk2(float lo, float hi) {
    u64 r; asm("mov.b64 %0,{%1,%2};" : "=l"(r) : "f"(lo), "f"(hi)); return r;
}
__device__ __forceinline__ void upk2(u64 v, float& lo, float& hi) {
    asm("mov.b64 {%0,%1},%2;" : "=f"(lo), "=f"(hi) : "l"(v));
}
__device__ __forceinline__ u64 fma2(u64 a, u64 b, u64 c) {
    u64 d; asm("fma.rn.f32x2 %0,%1,%2,%3;" : "=l"(d) : "l"(a), "l"(b), "l"(c)); return d;
}
__device__ __forceinline__ u64 mul2(u64 a, u64 b) {
    u64 d; asm("mul.rn.f32x2 %0,%1,%2;" : "=l"(d) : "l"(a), "l"(b)); return d;
}

// Ring-CNOT permutation: new_state[i] = old_state[perm_fwd(i)]
__device__ __forceinline__ int perm_fwd(int i) {
#pragma unroll
    for (int j = 11; j >= 0; j--) {
        int cb = 11 - j;
        int tb = (j == 11) ? 11 : (10 - j);
        i ^= ((i >> cb) & 1) << tb;
    }
    return i;
}
__device__ __forceinline__ int perm_inv(int i) {
#pragma unroll
    for (int j = 0; j < 12; j++) {
        int cb = 11 - j;
        int tb = (j == 11) ? 11 : (10 - j);
        i ^= ((i >> cb) & 1) << tb;
    }
    return i;
}

// Layout A (pass1 stores -> pass2 float4 loads):
//   physA(i) = i ^ (((i>>6)&7)<<1)     (bit0-preserving -> pairs adjacent)
// Layout B (pass2 stores -> next pass1 perm-loads, scalar float2):
//   physB(j) = j ^ (((j>>6)&7)<<1) ^ ((j>>9)&1)
//   (t-bit3 folded into addr bit 0 -> p2_store conflict-free; B is never
//    read vectorized so bit0 scrambling is harmless)
__device__ __forceinline__ int layB(int j) {
    return j ^ (((j >> 6) & 7) << 1) ^ ((j >> 9) & 1);
}

__global__ void __launch_bounds__(THREADS, 6) qsim_kernel(
    const float* __restrict__ x, const float* __restrict__ w,
    float* __restrict__ out)
{
    __shared__ float2 st[DIM];          // 32 KB state
    __shared__ float gc[48], gs[48];    // cos/sin (0-11 = merged encode+layer0)
    __shared__ float gt[48];            // tan(theta/2) (slots 12-47 consumed)
    __shared__ float sLA[16], sLB[16], sLC[16];  // product-state magnitude LUTs
    __shared__ float red[NQ];
    __shared__ float sS2;               // (prod c over gates 12..47)^2

    const int b = blockIdx.x;
    const int t = threadIdx.x;          // 0..63
    const int pt = perm_fwd(t);

    // Angles: slots 0-11 = x_q + w_{0,q} (RX fusion); 12-47 = w rows 1-3.
    if (t < 48) {
        float th = w[t];
        if (t < NQ) th += x[b * NQ + t];
        float ss, cc;
        sincosf(0.5f * th, &ss, &cc);
        gc[t] = cc; gs[t] = ss;
        gt[t] = ss / cc;
    }
    if (t < NQ) red[t] = 0.0f;
    __syncthreads();

    // Product-state magnitude LUTs over the three 4-bit nibbles (exact c,s).
    if (t < 48) {
        int grp = t >> 4;
        int h = t & 15;
        int qbase = grp * 4;
        float p = 1.0f;
#pragma unroll
        for (int q = 0; q < 4; q++)
            p *= ((h >> (3 - q)) & 1) ? gs[qbase + q] : gc[qbase + q];
        (grp == 0 ? sLA : grp == 1 ? sLB : sLC)[h] = p;
    }
    if (t == 0) {
        float S = 1.0f;
#pragma unroll
        for (int g = 12; g < 48; g++) S *= gc[g];
        sS2 = S * S;
    }

    // SoA packed state: slot k holds LOGICAL amps l=2k, 2k+1 (l = 6 bits).
    u64 X[32], Y[32];

    // pair-bit gate in tangent form on a freshly loaded pair, then pack.
    auto gate_pack = [&](float2 a0, float2 a1, float t1, int k) {
        float nx0 = fmaf( t1, a1.y, a0.x);
        float ny0 = fmaf(-t1, a1.x, a0.y);
        float nx1 = fmaf( t1, a0.y, a1.x);
        float ny1 = fmaf(-t1, a0.x, a1.y);
        X[k] = pk2(nx0, nx1);
        Y[k] = pk2(ny0, ny1);
    };

    // Packed tangent-form RX on pack-space bit pm (k in [0,32)).
    auto rxp = [&](int g, int pm) {
        float tg = gt[g];
        u64 t2 = pk2(tg, tg), m2 = pk2(-tg, -tg);
#pragma unroll
        for (int k = 0; k < 32; k++) {
            if (!(k & pm)) {
                int k1 = k | pm;
                u64 X0 = X[k], Y0 = Y[k], X1 = X[k1], Y1 = Y[k1];
                X[k]  = fma2(t2, Y1, X0);
                Y[k]  = fma2(m2, X1, Y0);
                X[k1] = fma2(t2, Y0, X1);
                Y[k1] = fma2(m2, X0, Y1);
            }
        }
    };
    // pass1: amps i=(l<<6)|t, register bits = qubits 0..5. Packed: qubits 0..4.
    auto packed5_p1 = [&](int g) {
        rxp(g, 16); rxp(g + 1, 8); rxp(g + 2, 4); rxp(g + 3, 2); rxp(g + 4, 1);
    };
    // pass2: amps i=(t<<6)|l, register bits = qubits 6..11. Packed: qubits 6..10.
    auto packed5_p2 = [&](int g) {
        rxp(g + 6, 16); rxp(g + 7, 8); rxp(g + 8, 4); rxp(g + 9, 2); rxp(g + 10, 1);
    };

    // Analytic product-state amplitude: amp = mag(pi) * (-i)^popc(pi)
    auto prod_amp = [&](int pi) -> float2 {
        float mag = sLA[pi >> 8] * sLB[(pi >> 4) & 15] * sLC[pi & 15];
        int kc = __popc(pi) & 3;
        float sm = __int_as_float(__float_as_int(mag) ^ (((kc + 1) & 2) << 30));
        return (kc & 1) ? make_float2(0.0f, sm) : make_float2(sm, 0.0f);
    };

    // pass1 perm-load (layers 2,3): amps i=(l<<6)|t from Layout B at
    // layB(perm_fwd(i)); load-time gate = qubit 5 (g+5) on l-bit 0.
    auto p1_load_perm = [&](int g) {
        float t1 = gt[g + 5];
#pragma unroll
        for (int k = 0; k < 32; k++) {
            int A0 = perm_fwd((2 * k) << 6) ^ pt;       // const ^ pt
            int A1 = perm_fwd((2 * k + 1) << 6) ^ pt;
            gate_pack(st[layB(A0)], st[layB(A1)], t1, k);
        }
    };
    // pass1 store into Layout A: phys = ((l<<6)|t) ^ ((l&7)<<1)
    auto p1_store = [&]() {
#pragma unroll
        for (int k = 0; k < 32; k++) {
            float x0, x1, y0, y1;
            upk2(X[k], x0, x1);
            upk2(Y[k], y0, y1);
            int l0 = 2 * k, l1 = 2 * k + 1;
            st[((l0 << 6) | t) ^ ((l0 & 7) << 1)] = make_float2(x0, y0);
            st[((l1 << 6) | t) ^ ((l1 & 7) << 1)] = make_float2(x1, y1);
        }
    };
    // pass2 float4 load from Layout A: phys4 = (t<<5)|(k^(t&7)) holds logical
    // pack k (amps (t<<6)|2k, +1). Load-time gate = qubit 11 (g+11).
    auto p2_load = [&](int g) {
        float t1 = gt[g + 11];
        const float4* st4 = reinterpret_cast<const float4*>(st);
        int base = t << 5, key = t & 7;
#pragma unroll
        for (int k = 0; k < 32; k++) {
            float4 v = st4[base | (k ^ key)];
            gate_pack(make_float2(v.x, v.y), make_float2(v.z, v.w), t1, k);
        }
    };
    // pass2 store into Layout B: phys = (t<<6) | (l ^ (((t&7)<<1)|((t>>3)&1)))
    // (thread-private 64-entry block; no intra-pass sync needed)
    auto p2_store = [&]() {
        int base = (t << 6);
        int key = ((t & 7) << 1) | ((t >> 3) & 1);
#pragma unroll
        for (int k = 0; k < 32; k++) {
            float x0, x1, y0, y1;
            upk2(X[k], x0, x1);
            upk2(Y[k], y0, y1);
            st[base | ((2 * k) ^ key)]     = make_float2(x0, y0);
            st[base | ((2 * k + 1) ^ key)] = make_float2(x1, y1);
        }
    };

    __syncthreads();  // LUTs + sS2 ready

    // ---- Layer 1 (gates 12-23) ----
    // pass1: analytic amps at perm-permuted indices of the merged product state
    {
        float t1 = gt[12 + 5];
#pragma unroll
        for (int k = 0; k < 32; k++)
            gate_pack(prod_amp(perm_fwd((2 * k) << 6) ^ pt),
                      prod_amp(perm_fwd((2 * k + 1) << 6) ^ pt), t1, k);
        packed5_p1(12);
        p1_store(); __syncthreads();
        p2_load(12); packed5_p2(12); p2_store(); __syncthreads();
    }

    // ---- Layers 2,3 (gates 24-35, 36-47) ----
#pragma unroll 1
    for (int layer = 2; layer <= 3; layer++) {
        int g = layer * 12;
        p1_load_perm(g);
        packed5_p1(g);
        __syncthreads();               // scattered reads done before overwrite
        p1_store(); __syncthreads();
        p2_load(g); packed5_p2(g);
        if (layer < 3) { p2_store(); __syncthreads(); }
        // layer 3: stays in registers; final perm folded into readout
    }

    // ---- Readout: <Z_q> = S^2 * sum_i p_i * (1-2*bit_{11-q}(perm_inv(i))) ----
    u64 acc2[NQ];
    const u64 spp = pk2( 1.0f,  1.0f), spm = pk2( 1.0f, -1.0f);
    const u64 smp = pk2(-1.0f,  1.0f), smm = pk2(-1.0f, -1.0f);
#pragma unroll
    for (int q = 0; q < NQ; q++) acc2[q] = 0ull;
#pragma unroll
    for (int k = 0; k < 32; k++) {
        u64 P = fma2(X[k], X[k], mul2(Y[k], Y[k]));
        const int pil0 = perm_inv(2 * k);      // compile-time constants
        const int pil1 = perm_inv(2 * k + 1);
#pragma unroll
        for (int q = 0; q < NQ; q++) {
            bool n0 = (pil0 >> (11 - q)) & 1;
            bool n1 = (pil1 >> (11 - q)) & 1;
            u64 sgn = n0 ? (n1 ? smm : smp) : (n1 ? spm : spp);
            acc2[q] = fma2(sgn, P, acc2[q]);
        }
    }
    float acc[NQ];
    {
        int pit = perm_inv(t << 6);   // runtime per-thread sign factor
#pragma unroll
        for (int q = 0; q < NQ; q++) {
            float a0, a1;
            upk2(acc2[q], a0, a1);
            float s = a0 + a1;
            acc[q] = __int_as_float(__float_as_int(s) ^
                                    (((pit >> (11 - q)) & 1) << 31));
        }
    }
#pragma unroll
    for (int off = 16; off > 0; off >>= 1) {
#pragma unroll
        for (int q = 0; q < NQ; q++)
            acc[q] += __shfl_xor_sync(0xffffffffu, acc[q], off);
    }
    if ((t & 31) == 0) {
#pragma unroll
        for (int q = 0; q < NQ; q++) atomicAdd(&red[q], acc[q]);
    }
    __syncthreads();
    if (t < NQ) out[b * NQ + t] = red[t] * sS2;  // apply deferred scale once
}

extern "C" void kernel_launch(void* const* d_in, const int* in_sizes, int n_in,
                              void* d_out, int out_size) {
    const float* x = (const float*)d_in[0];   // (64,128,12) float32
    const float* w = (const float*)d_in[1];   // (4,12) float32
    float* out = (float*)d_out;               // (64,128,12) float32
    int B = in_sizes[0] / NQ;                 // 8192
    qsim_kernel<<<B, THREADS>>>(x, w, out);
}